// round 5
// baseline (speedup 1.0000x reference)
#include <cuda_runtime.h>
#include <math.h>
#include <stdint.h>

// ---------------- problem constants ----------------
#define Dm   1024
#define Tq   512
#define NB   4
#define NH   16
#define HDm  64
#define KTOT 1792
#define MR   2048        // NB*Tq rows
#define DFF  4096

// ---------------- scratch (device globals; no allocation) ----------------
__device__ float g_mod[NB * 6 * Dm];
__device__ float g_xnorm[MR * Dm];
__device__ float g_q0[MR * Dm];
__device__ float g_qad[3 * MR * Dm];
__device__ float g_hidden[3 * MR * 256];
__device__ float g_kcat[NB * KTOT * Dm];
__device__ float g_vcat[NB * KTOT * Dm];
__device__ float g_attnout[MR * Dm];
__device__ float g_xa[MR * Dm];
__device__ float g_hln[MR * Dm];
__device__ float g_hff[MR * DFF];
__device__ float g_rcos[Tq * 32];
__device__ float g_rsin[Tq * 32];

// ---------------- helpers ----------------
__device__ __forceinline__ float to_tf32(float x) {
    float y;
    asm("cvt.rna.tf32.f32 %0, %1;" : "=f"(y) : "f"(x));
    return y;
}

__device__ __forceinline__ void mma8(float* c, const uint32_t* a, const uint32_t* b) {
    asm volatile(
        "mma.sync.aligned.m16n8k8.row.col.f32.tf32.tf32.f32 "
        "{%0,%1,%2,%3},{%4,%5,%6,%7},{%8,%9},{%0,%1,%2,%3};\n"
        : "+f"(c[0]), "+f"(c[1]), "+f"(c[2]), "+f"(c[3])
        : "r"(a[0]), "r"(a[1]), "r"(a[2]), "r"(a[3]), "r"(b[0]), "r"(b[1]));
}

// ================== tf32 GEMM core: C = A @ W^T + bias (+ epilogue) ==========
// Shared layout: [m][perm(k)] with perm(k) = (k&8) + ((k&3)<<1) + ((k>>2)&1),
// stride 20 floats -> every fragment load is one LDS.64, conflict-free.
// Tile 128x128x16, 8 warps each 64x32. Identity or segment out-row remap.
template<int EPI, int Kc, int Nc>
__device__ __forceinline__ void gemm_core(
    const float* __restrict__ A, const float* __restrict__ W,
    const float* __restrict__ bias, float* __restrict__ C,
    int Lb, int outBatchRows, int outRowOff,
    const float* __restrict__ res, const float* __restrict__ mod, int gateOff,
    float (*As)[128][20], float (*Bs)[128][20])
{
    int tid  = threadIdx.x;
    int wid  = tid >> 5;
    int lane = tid & 31;
    int g   = lane >> 2;
    int tc2 = (lane & 3) * 2;
    int warpM = (wid & 1) * 64;
    int warpN = (wid >> 1) * 32;

    int row0 = blockIdx.y * 128;
    int col0 = blockIdx.x * 128;

    int ldRow  = tid >> 1;
    int ldHalf = (tid & 1) * 8;
    const float* Ag = A + (size_t)(row0 + ldRow) * Kc + ldHalf;
    const float* Wg = W + (size_t)(col0 + ldRow) * Kc + ldHalf;

    float acc[4][4][4];
    #pragma unroll
    for (int mi = 0; mi < 4; mi++)
        #pragma unroll
        for (int ni = 0; ni < 4; ni++)
            #pragma unroll
            for (int e = 0; e < 4; e++) acc[mi][ni][e] = 0.f;

    // prologue
    {
        float4 a0 = *(const float4*)Ag;
        float4 a1 = *(const float4*)(Ag + 4);
        float4 b0 = *(const float4*)Wg;
        float4 b1 = *(const float4*)(Wg + 4);
        float av[8] = {a0.x, a0.y, a0.z, a0.w, a1.x, a1.y, a1.z, a1.w};
        float bv[8] = {b0.x, b0.y, b0.z, b0.w, b1.x, b1.y, b1.z, b1.w};
        #pragma unroll
        for (int j = 0; j < 4; j++) {
            float2 pa = {to_tf32(av[j]), to_tf32(av[j + 4])};
            float2 pb = {to_tf32(bv[j]), to_tf32(bv[j + 4])};
            *(float2*)&As[0][ldRow][ldHalf + j * 2] = pa;
            *(float2*)&Bs[0][ldRow][ldHalf + j * 2] = pb;
        }
    }
    __syncthreads();

    const int NIT = Kc >> 4;
    float4 na0, na1, nb0, nb1;
    #pragma unroll 1
    for (int it = 0; it < NIT; it++) {
        int buf = it & 1;
        if (it + 1 < NIT) {
            const float* Ag2 = Ag + (it + 1) * 16;
            const float* Wg2 = Wg + (it + 1) * 16;
            na0 = *(const float4*)Ag2;
            na1 = *(const float4*)(Ag2 + 4);
            nb0 = *(const float4*)Wg2;
            nb1 = *(const float4*)(Wg2 + 4);
        }
        #pragma unroll
        for (int kb = 0; kb < 16; kb += 8) {
            uint32_t af[4][4];
            #pragma unroll
            for (int mi = 0; mi < 4; mi++) {
                int r = warpM + mi * 16 + g;
                float2 p0 = *(const float2*)&As[buf][r][kb + tc2];
                float2 p1 = *(const float2*)&As[buf][r + 8][kb + tc2];
                af[mi][0] = __float_as_uint(p0.x);
                af[mi][1] = __float_as_uint(p1.x);
                af[mi][2] = __float_as_uint(p0.y);
                af[mi][3] = __float_as_uint(p1.y);
            }
            uint32_t bf_[4][2];
            #pragma unroll
            for (int ni = 0; ni < 4; ni++) {
                int cN = warpN + ni * 8 + g;
                float2 pb = *(const float2*)&Bs[buf][cN][kb + tc2];
                bf_[ni][0] = __float_as_uint(pb.x);
                bf_[ni][1] = __float_as_uint(pb.y);
            }
            #pragma unroll
            for (int mi = 0; mi < 4; mi++)
                #pragma unroll
                for (int ni = 0; ni < 4; ni++)
                    mma8(acc[mi][ni], af[mi], bf_[ni]);
        }
        if (it + 1 < NIT) {
            int nb = buf ^ 1;
            float av[8] = {na0.x, na0.y, na0.z, na0.w, na1.x, na1.y, na1.z, na1.w};
            float bv[8] = {nb0.x, nb0.y, nb0.z, nb0.w, nb1.x, nb1.y, nb1.z, nb1.w};
            #pragma unroll
            for (int j = 0; j < 4; j++) {
                float2 pa = {to_tf32(av[j]), to_tf32(av[j + 4])};
                float2 pb = {to_tf32(bv[j]), to_tf32(bv[j + 4])};
                *(float2*)&As[nb][ldRow][ldHalf + j * 2] = pa;
                *(float2*)&Bs[nb][ldRow][ldHalf + j * 2] = pb;
            }
            __syncthreads();
        }
    }

    // epilogue
    int tc = tc2 >> 1;
    #pragma unroll
    for (int mi = 0; mi < 4; mi++) {
        #pragma unroll
        for (int ib = 0; ib < 2; ib++) {
            int m = row0 + warpM + mi * 16 + g + ib * 8;
            int orow = (m / Lb) * outBatchRows + outRowOff + (m % Lb);
            const float* resr = (EPI == 2) ? res + (size_t)m * Nc : nullptr;
            const float* gr   = (EPI == 2) ? mod + (m / Tq) * (6 * Dm) + gateOff : nullptr;
            #pragma unroll
            for (int ni = 0; ni < 4; ni++) {
                int n = col0 + warpN + ni * 8 + tc * 2;
                float v0 = acc[mi][ni][ib * 2 + 0] + bias[n];
                float v1 = acc[mi][ni][ib * 2 + 1] + bias[n + 1];
                if (EPI == 1) {
                    v0 = 0.5f * v0 * (1.f + erff(v0 * 0.70710678118654752f));
                    v1 = 0.5f * v1 * (1.f + erff(v1 * 0.70710678118654752f));
                }
                if (EPI == 2) {
                    v0 = resr[n] + gr[n] * v0;
                    v1 = resr[n + 1] + gr[n + 1] * v1;
                }
                float2 o2 = {v0, v1};
                *(float2*)&C[(size_t)orow * Nc + n] = o2;
            }
        }
    }
}

// ---- batched K/V/Q projections: z = 0..3 K(src), 4..7 V(src), 8 Q ----
__global__ __launch_bounds__(256, 2) void kvq_kernel(
    const float* __restrict__ xnorm, const float* __restrict__ bev,
    const float* __restrict__ vl, const float* __restrict__ reas,
    const float* __restrict__ k_w, const float* __restrict__ k_b,
    const float* __restrict__ v_w, const float* __restrict__ v_b,
    const float* __restrict__ qw, const float* __restrict__ qb,
    float* __restrict__ kcat, float* __restrict__ vcat, float* __restrict__ q0)
{
    __shared__ __align__(16) float As[2][128][20];
    __shared__ __align__(16) float Bs[2][128][20];
    int z = blockIdx.z;
    const float* A; const float* W; const float* bias; float* C;
    int Lb, oBR, oRO;
    if (z < 8) {
        int src = z & 3;
        if (src == 3 && blockIdx.y >= 8) return;
        A = (src == 0) ? xnorm : (src == 1) ? bev : (src == 2) ? vl : reas;
        bool isV = z >= 4;
        W    = (isV ? v_w : k_w) + (size_t)src * Dm * Dm;
        bias = (isV ? v_b : k_b) + src * Dm;
        C    = isV ? vcat : kcat;
        Lb = (src == 3) ? 256 : 512;
        oBR = KTOT; oRO = src * 512;
    } else {
        A = xnorm; W = qw; bias = qb; C = q0;
        Lb = 1 << 30; oBR = 0; oRO = 0;
    }
    gemm_core<0, 1024, 1024>(A, W, bias, C, Lb, oBR, oRO, nullptr, nullptr, 0, As, Bs);
}

// ---- batched adapter hidden: z = 0..2 ----
__global__ __launch_bounds__(256, 2) void adapter_h_kernel(
    const float* __restrict__ xnorm, const float* __restrict__ qa_w,
    const float* __restrict__ qa_b, float* __restrict__ hidden)
{
    __shared__ __align__(16) float As[2][128][20];
    __shared__ __align__(16) float Bs[2][128][20];
    int z = blockIdx.z;
    gemm_core<0, 1024, 256>(xnorm, qa_w + (size_t)z * 256 * Dm, qa_b + z * 256,
                            hidden + (size_t)z * MR * 256,
                            1 << 30, 0, 0, nullptr, nullptr, 0, As, Bs);
}

// ---- batched adapter out: z = 0..2 ----
__global__ __launch_bounds__(256, 2) void adapter_o_kernel(
    const float* __restrict__ hidden, const float* __restrict__ qa_out_w,
    const float* __restrict__ qa_out_b, float* __restrict__ qad)
{
    __shared__ __align__(16) float As[2][128][20];
    __shared__ __align__(16) float Bs[2][128][20];
    int z = blockIdx.z;
    gemm_core<0, 256, 1024>(hidden + (size_t)z * MR * 256, qa_out_w, qa_out_b,
                            qad + (size_t)z * MR * Dm,
                            1 << 30, 0, 0, nullptr, nullptr, 0, As, Bs);
}

// ---- generic (identity remap) GEMM ----
template<int EPI, int Kc, int Nc>
__global__ __launch_bounds__(256, 2) void gemm_kernel(
    const float* __restrict__ A, const float* __restrict__ W,
    const float* __restrict__ bias, float* __restrict__ C,
    const float* __restrict__ res, const float* __restrict__ mod, int gateOff)
{
    __shared__ __align__(16) float As[2][128][20];
    __shared__ __align__(16) float Bs[2][128][20];
    gemm_core<EPI, Kc, Nc>(A, W, bias, C, 1 << 30, 0, 0, res, mod, gateOff, As, Bs);
}

// ---------------- mod = silu(cond) @ adaln_w^T + adaln_b ----------------
__global__ __launch_bounds__(256) void mod_kernel(const float* __restrict__ cond,
                                                  const float* __restrict__ W,
                                                  const float* __restrict__ bb,
                                                  float* __restrict__ mod)
{
    int b = blockIdx.y;
    __shared__ float sc[Dm];
    for (int i = threadIdx.x; i < Dm; i += 256) {
        float c = cond[b * Dm + i];
        sc[i] = c / (1.f + expf(-c));
    }
    __syncthreads();
    int w = threadIdx.x >> 5, lane = threadIdx.x & 31;
    int n = blockIdx.x * 8 + w;
    const float* wr = W + (size_t)n * Dm;
    float acc = 0.f;
    for (int k = lane; k < Dm; k += 32) acc += sc[k] * wr[k];
    #pragma unroll
    for (int o = 16; o; o >>= 1) acc += __shfl_xor_sync(~0u, acc, o);
    if (lane == 0) mod[b * 6 * Dm + n] = acc + bb[n];
}

// ---------------- LayerNorm + AdaLN modulate ----------------
__global__ __launch_bounds__(256) void ln_mod_kernel(const float* __restrict__ x,
                                                     const float* __restrict__ w,
                                                     const float* __restrict__ bvec,
                                                     const float* __restrict__ mod,
                                                     int shiftOff, int scaleOff,
                                                     float* __restrict__ out)
{
    int row = blockIdx.x;
    int tid = threadIdx.x;
    float4 v = ((const float4*)(x + (size_t)row * Dm))[tid];
    float s = v.x + v.y + v.z + v.w;
    float q = v.x * v.x + v.y * v.y + v.z * v.z + v.w * v.w;
    __shared__ float rs[8], rq[8];
    #pragma unroll
    for (int o = 16; o; o >>= 1) {
        s += __shfl_xor_sync(~0u, s, o);
        q += __shfl_xor_sync(~0u, q, o);
    }
    if ((tid & 31) == 0) { rs[tid >> 5] = s; rq[tid >> 5] = q; }
    __syncthreads();
    float sum = 0.f, sq = 0.f;
    #pragma unroll
    for (int i = 0; i < 8; i++) { sum += rs[i]; sq += rq[i]; }
    float mean = sum * (1.f / Dm);
    float var  = sq * (1.f / Dm) - mean * mean;
    float inv  = rsqrtf(var + 1e-5f);
    const float* ms = mod + (row / Tq) * (6 * Dm);
    int d = tid * 4;
    float in[4] = {v.x, v.y, v.z, v.w};
    float4 ov;
    float* po = (float*)&ov;
    #pragma unroll
    for (int e = 0; e < 4; e++) {
        float xn = (in[e] - mean) * inv * w[d + e] + bvec[d + e];
        po[e] = xn * (1.f + ms[scaleOff + d + e]) + ms[shiftOff + d + e];
    }
    ((float4*)(out + (size_t)row * Dm))[tid] = ov;
}

// ---------------- RoPE table ----------------
__global__ void rope_table_kernel(float* __restrict__ c, float* __restrict__ s)
{
    int pos = blockIdx.x, j = threadIdx.x;
    float ang = (float)pos * expf(-(float)j * (9.2103403719761836f / 32.f));
    float sn, cs;
    sincosf(ang, &sn, &cs);
    c[pos * 32 + j] = cs;
    s[pos * 32 + j] = sn;
}

// ---------------- QK post: per-head RMSNorm (+ optional RoPE) ----------------
__global__ __launch_bounds__(256) void qkpost_kernel(float* __restrict__ buf,
                                                     const float* __restrict__ w,
                                                     const float* __restrict__ rc,
                                                     const float* __restrict__ rs,
                                                     int mode)
{
    int row = blockIdx.x, tid = threadIdx.x;
    float* rp = buf + (size_t)row * Dm;
    float4 v = ((float4*)rp)[tid];
    float ss = v.x * v.x + v.y * v.y + v.z * v.z + v.w * v.w;
    ss += __shfl_xor_sync(~0u, ss, 1, 16);
    ss += __shfl_xor_sync(~0u, ss, 2, 16);
    ss += __shfl_xor_sync(~0u, ss, 4, 16);
    ss += __shfl_xor_sync(~0u, ss, 8, 16);
    float inv = rsqrtf(ss * (1.f / 64.f) + 1e-6f);
    int dl = (tid & 15) * 4;
    float nv[4] = {v.x * inv * w[dl], v.y * inv * w[dl + 1],
                   v.z * inv * w[dl + 2], v.w * inv * w[dl + 3]};
    int pos = -1;
    if (mode == 1) pos = row & (Tq - 1);
    else if (mode == 2) {
        int r = row % KTOT;
        pos = (r < 512) ? r : (r < 1024) ? r - 512 : (r < 1536) ? r - 1024 : r - 1536;
    }
    if (pos >= 0) {
        float pv[4];
        #pragma unroll
        for (int e = 0; e < 4; e++) pv[e] = __shfl_xor_sync(~0u, nv[e], 8, 16);
        bool firstHalf = dl < 32;
        int jb = dl & 31;
        float4 c4 = *(const float4*)&rc[pos * 32 + jb];
        float4 s4 = *(const float4*)&rs[pos * 32 + jb];
        float cse[4] = {c4.x, c4.y, c4.z, c4.w};
        float sne[4] = {s4.x, s4.y, s4.z, s4.w};
        #pragma unroll
        for (int e = 0; e < 4; e++) {
            nv[e] = firstHalf ? (nv[e] * cse[e] - pv[e] * sne[e])
                              : (nv[e] * cse[e] + pv[e] * sne[e]);
        }
    }
    float4 o = {nv[0], nv[1], nv[2], nv[3]};
    ((float4*)rp)[tid] = o;
}

// ---------------- Flash attention (joint softmax over 4 segments) ----------------
__global__ __launch_bounds__(256) void flash_kernel(
    const float* __restrict__ q0, const float* __restrict__ q1,
    const float* __restrict__ q2, const float* __restrict__ q3,
    const float* __restrict__ kcat, const float* __restrict__ vcat,
    const float* __restrict__ temps, const float* __restrict__ sbias,
    const float* __restrict__ gating, float* __restrict__ outp)
{
    extern __shared__ float sm[];
    float* Qs = sm;               // [64 d][68]
    float* Ks = sm + 64 * 68;     // [64 d][68]
    float* Vs = sm + 2 * 64 * 68; // [key][68]
    float* Ps = sm + 3 * 64 * 68; // [qrow][68]
    __shared__ float m_sh[64], l_sh[64];

    int tid = threadIdx.x, tx = tid & 15, ty = tid >> 4;
    int h = blockIdx.y, b = blockIdx.z;
    int qbase = b * Tq + blockIdx.x * 64;
    int lr = tid >> 2, lq = tid & 3;

    if (tid < 64) { m_sh[tid] = -1e30f; l_sh[tid] = 0.f; }
    float O[4][4];
    #pragma unroll
    for (int i = 0; i < 4; i++)
        #pragma unroll
        for (int j = 0; j < 4; j++) O[i][j] = 0.f;

    const float* qp[4] = {q0, q1, q2, q3};
    const int SEGL[4] = {512, 512, 512, 256};
    const int SEGO[4] = {0, 512, 1024, 1536};
    float rg = tanhf(gating[0]);

    for (int seg = 0; seg < 4; seg++) {
        float tt = temps[seg];
        float sp = tt > 20.f ? tt : log1pf(expf(tt));
        float scale = 0.125f * (1.f + sp);
        float sb = sbias[seg];
        if (seg == 3) { scale *= rg; sb *= rg; }

        {
            const float* src = qp[seg] + (size_t)(qbase + lr) * Dm + h * HDm + lq * 16;
            #pragma unroll
            for (int q4 = 0; q4 < 4; q4++) {
                float4 t4 = ((const float4*)src)[q4];
                int d = lq * 16 + q4 * 4;
                Qs[(d + 0) * 68 + lr] = t4.x;
                Qs[(d + 1) * 68 + lr] = t4.y;
                Qs[(d + 2) * 68 + lr] = t4.z;
                Qs[(d + 3) * 68 + lr] = t4.w;
            }
        }
        int nt = SEGL[seg] >> 6;
        for (int kt = 0; kt < nt; kt++) {
            int krow = b * KTOT + SEGO[seg] + kt * 64;
            {
                const float* srk = kcat + (size_t)(krow + lr) * Dm + h * HDm + lq * 16;
                const float* srv = vcat + (size_t)(krow + lr) * Dm + h * HDm + lq * 16;
                #pragma unroll
                for (int q4 = 0; q4 < 4; q4++) {
                    float4 t4 = ((const float4*)srk)[q4];
                    int d = lq * 16 + q4 * 4;
                    Ks[(d + 0) * 68 + lr] = t4.x;
                    Ks[(d + 1) * 68 + lr] = t4.y;
                    Ks[(d + 2) * 68 + lr] = t4.z;
                    Ks[(d + 3) * 68 + lr] = t4.w;
                    *(float4*)&Vs[lr * 68 + d] = ((const float4*)srv)[q4];
                }
            }
            __syncthreads();

            float s[4][4];
            #pragma unroll
            for (int i = 0; i < 4; i++)
                #pragma unroll
                for (int j = 0; j < 4; j++) s[i][j] = 0.f;
            #pragma unroll 8
            for (int d = 0; d < 64; d++) {
                float4 qa = *(const float4*)&Qs[d * 68 + ty * 4];
                float4 kb = *(const float4*)&Ks[d * 68 + tx * 4];
                float qm[4] = {qa.x, qa.y, qa.z, qa.w};
                float kn[4] = {kb.x, kb.y, kb.z, kb.w};
                #pragma unroll
                for (int i = 0; i < 4; i++)
                    #pragma unroll
                    for (int j = 0; j < 4; j++)
                        s[i][j] += qm[i] * kn[j];
            }

            float mn[4], fac[4], rsum[4];
            #pragma unroll
            for (int i = 0; i < 4; i++) {
                float tm = -1e30f;
                #pragma unroll
                for (int j = 0; j < 4; j++) {
                    s[i][j] = s[i][j] * scale + sb;
                    tm = fmaxf(tm, s[i][j]);
                }
                #pragma unroll
                for (int o = 8; o; o >>= 1)
                    tm = fmaxf(tm, __shfl_xor_sync(~0u, tm, o, 16));
                float mo = m_sh[ty * 4 + i];
                mn[i] = fmaxf(mo, tm);
                fac[i] = __expf(mo - mn[i]);
                float sum = 0.f;
                #pragma unroll
                for (int j = 0; j < 4; j++) {
                    float p = __expf(s[i][j] - mn[i]);
                    s[i][j] = p;
                    sum += p;
                    Ps[(ty * 4 + i) * 68 + tx * 4 + j] = p;
                }
                #pragma unroll
                for (int o = 8; o; o >>= 1)
                    sum += __shfl_xor_sync(~0u, sum, o, 16);
                rsum[i] = sum;
                #pragma unroll
                for (int j = 0; j < 4; j++) O[i][j] *= fac[i];
            }
            __syncthreads();
            if (tx == 0) {
                #pragma unroll
                for (int i = 0; i < 4; i++) {
                    m_sh[ty * 4 + i] = mn[i];
                    l_sh[ty * 4 + i] = l_sh[ty * 4 + i] * fac[i] + rsum[i];
                }
            }
            #pragma unroll 8
            for (int k = 0; k < 64; k++) {
                float4 vb = *(const float4*)&Vs[k * 68 + tx * 4];
                float p0 = Ps[(ty * 4 + 0) * 68 + k];
                float p1 = Ps[(ty * 4 + 1) * 68 + k];
                float p2 = Ps[(ty * 4 + 2) * 68 + k];
                float p3 = Ps[(ty * 4 + 3) * 68 + k];
                O[0][0] += p0 * vb.x; O[0][1] += p0 * vb.y; O[0][2] += p0 * vb.z; O[0][3] += p0 * vb.w;
                O[1][0] += p1 * vb.x; O[1][1] += p1 * vb.y; O[1][2] += p1 * vb.z; O[1][3] += p1 * vb.w;
                O[2][0] += p2 * vb.x; O[2][1] += p2 * vb.y; O[2][2] += p2 * vb.z; O[2][3] += p2 * vb.w;
                O[3][0] += p3 * vb.x; O[3][1] += p3 * vb.y; O[3][2] += p3 * vb.z; O[3][3] += p3 * vb.w;
            }
            __syncthreads();
        }
    }
    #pragma unroll
    for (int i = 0; i < 4; i++) {
        float invl = 1.f / l_sh[ty * 4 + i];
        float* dst = outp + (size_t)(qbase + ty * 4 + i) * Dm + h * HDm + tx * 4;
        #pragma unroll
        for (int j = 0; j < 4; j++) dst[j] = O[i][j] * invl;
    }
}

// ---------------- launch ----------------
static float* symaddr(const void* s) {
    void* p = nullptr;
    cudaGetSymbolAddress(&p, s);
    return (float*)p;
}

extern "C" void kernel_launch(void* const* d_in, const int* in_sizes, int n_in,
                              void* d_out, int out_size)
{
    const float* x        = (const float*)d_in[0];
    const float* bev      = (const float*)d_in[1];
    const float* vl       = (const float*)d_in[2];
    const float* reas     = (const float*)d_in[3];
    const float* cond     = (const float*)d_in[4];
    const float* ln_pre_w = (const float*)d_in[5];
    const float* ln_pre_b = (const float*)d_in[6];
    const float* adaln_w  = (const float*)d_in[7];
    const float* adaln_b  = (const float*)d_in[8];
    const float* q_proj_w = (const float*)d_in[9];
    const float* q_proj_b = (const float*)d_in[10];
    const float* qa_w     = (const float*)d_in[11];
    const float* qa_b     = (const float*)d_in[12];
    const float* qa_out_w = (const float*)d_in[13];
    const float* qa_out_b = (const float*)d_in[14];
    const float* k_w      = (const float*)d_in[15];
    const float* k_b      = (const float*)d_in[16];
    const float* v_w      = (const float*)d_in[17];
    const float* v_b      = (const float*)d_in[18];
    const float* o_w      = (const float*)d_in[19];
    const float* o_b      = (const float*)d_in[20];
    const float* qn_w     = (const float*)d_in[21];
    const float* kn_w     = (const float*)d_in[22];
    const float* gating   = (const float*)d_in[23];
    const float* temps    = (const float*)d_in[24];
    const float* sbias    = (const float*)d_in[25];
    const float* ffn_ln_w = (const float*)d_in[26];
    const float* ffn_ln_b = (const float*)d_in[27];
    const float* ffn_w1   = (const float*)d_in[28];
    const float* ffn_b1   = (const float*)d_in[29];
    const float* ffn_w2   = (const float*)d_in[30];
    const float* ffn_b2   = (const float*)d_in[31];
    float* out = (float*)d_out;

    float* p_mod    = symaddr(g_mod);
    float* p_xnorm  = symaddr(g_xnorm);
    float* p_q0     = symaddr(g_q0);
    float* p_qad    = symaddr(g_qad);
    float* p_hidden = symaddr(g_hidden);
    float* p_kcat   = symaddr(g_kcat);
    float* p_vcat   = symaddr(g_vcat);
    float* p_attn   = symaddr(g_attnout);
    float* p_xa     = symaddr(g_xa);
    float* p_hln    = symaddr(g_hln);
    float* p_hff    = symaddr(g_hff);
    float* p_rcos   = symaddr(g_rcos);
    float* p_rsin   = symaddr(g_rsin);

    // 0) RoPE tables
    rope_table_kernel<<<Tq, 32>>>(p_rcos, p_rsin);

    // 1) AdaLN modulation
    mod_kernel<<<dim3(6 * Dm / 8, NB), 256>>>(cond, adaln_w, adaln_b, p_mod);

    // 2) pre-LN + modulate
    ln_mod_kernel<<<MR, 256>>>(x, ln_pre_w, ln_pre_b, p_mod, 0, Dm, p_xnorm);

    // 3) K/V (4 sources) + Q in one batched launch
    kvq_kernel<<<dim3(8, 16, 9), 256>>>(
        p_xnorm, bev, vl, reas, k_w, k_b, v_w, v_b, q_proj_w, q_proj_b,
        p_kcat, p_vcat, p_q0);

    // 4) adapters (batched over 3)
    adapter_h_kernel<<<dim3(2, 16, 3), 256>>>(p_xnorm, qa_w, qa_b, p_hidden);
    adapter_o_kernel<<<dim3(8, 16, 3), 256>>>(p_hidden, qa_out_w, qa_out_b, p_qad);

    // 5) QK-norm + RoPE
    qkpost_kernel<<<MR, 256>>>(p_q0, qn_w, p_rcos, p_rsin, 1);
    qkpost_kernel<<<3 * MR, 256>>>(p_qad, qn_w, p_rcos, p_rsin, 0);
    qkpost_kernel<<<NB * KTOT, 256>>>(p_kcat, kn_w, p_rcos, p_rsin, 2);

    // 6) flash attention
    int smemBytes = 4 * 64 * 68 * (int)sizeof(float);
    cudaFuncSetAttribute(flash_kernel, cudaFuncAttributeMaxDynamicSharedMemorySize, smemBytes);
    flash_kernel<<<dim3(Tq / 64, NH, NB), 256, smemBytes>>>(
        p_q0, p_qad, p_qad + (size_t)MR * Dm, p_qad + (size_t)2 * MR * Dm,
        p_kcat, p_vcat, temps, sbias, gating, p_attn);

    // 7) o-proj + residual + gate_attn
    gemm_kernel<2, 1024, 1024><<<dim3(8, 16), 256>>>(
        p_attn, o_w, o_b, p_xa, x, p_mod, 2 * Dm);

    // 8) FFN
    ln_mod_kernel<<<MR, 256>>>(p_xa, ffn_ln_w, ffn_ln_b, p_mod, 3 * Dm, 4 * Dm, p_hln);
    gemm_kernel<1, 1024, 4096><<<dim3(32, 16), 256>>>(
        p_hln, ffn_w1, ffn_b1, p_hff, nullptr, nullptr, 0);
    gemm_kernel<2, 4096, 1024><<<dim3(8, 16), 256>>>(
        p_hff, ffn_w2, ffn_b2, out, p_xa, p_mod, 5 * Dm);
}

// round 6
// speedup vs baseline: 1.6743x; 1.6743x over previous
#include <cuda_runtime.h>
#include <math.h>
#include <stdint.h>

// ---------------- problem constants ----------------
#define Dm   1024
#define Tq   512
#define NB   4
#define NH   16
#define HDm  64
#define KTOT 1792
#define MR   2048        // NB*Tq rows
#define DFF  4096

// ---------------- scratch (device globals; no allocation) ----------------
__device__ float g_mod[NB * 6 * Dm];
__device__ float g_xnorm[MR * Dm];
__device__ float g_q0[MR * Dm];
__device__ float g_qad[3 * MR * Dm];
__device__ float g_hidden[3 * MR * 256];
__device__ float g_kcat[NB * KTOT * Dm];
__device__ float g_vcat[NB * KTOT * Dm];
__device__ float g_attnout[MR * Dm];
__device__ float g_xa[MR * Dm];
__device__ float g_hln[MR * Dm];
__device__ float g_hff[MR * DFF];
__device__ float g_rcos[Tq * 32];
__device__ float g_rsin[Tq * 32];

// ---------------- helpers ----------------
__device__ __forceinline__ float to_tf32(float x) {
    float y;
    asm("cvt.rna.tf32.f32 %0, %1;" : "=f"(y) : "f"(x));
    return y;
}

__device__ __forceinline__ void mma8(float* c, const uint32_t* a, const uint32_t* b) {
    asm volatile(
        "mma.sync.aligned.m16n8k8.row.col.f32.tf32.tf32.f32 "
        "{%0,%1,%2,%3},{%4,%5,%6,%7},{%8,%9},{%0,%1,%2,%3};\n"
        : "+f"(c[0]), "+f"(c[1]), "+f"(c[2]), "+f"(c[3])
        : "r"(a[0]), "r"(a[1]), "r"(a[2]), "r"(a[3]), "r"(b[0]), "r"(b[1]));
}

// ================== tf32 GEMM core: C = A @ W^T + bias (+ epilogue) ==========
// Shared layout: [k][m] stride 136 (round-3 proven): fragment-load bank =
// 8*tc + g -> bijection over 32 banks, conflict-free LDS.32.
// Tile 128x128x16, 8 warps each 64x32 (4x4 m16n8k8).
template<int EPI, int Kc, int Nc>
__device__ __forceinline__ void gemm_core(
    const float* __restrict__ A, const float* __restrict__ W,
    const float* __restrict__ bias, float* __restrict__ C,
    int Lb, int outBatchRows, int outRowOff,
    const float* __restrict__ res, const float* __restrict__ mod, int gateOff,
    float (*As)[16][136], float (*Bs)[16][136])
{
    int tid  = threadIdx.x;
    int wid  = tid >> 5;
    int lane = tid & 31;
    int g  = lane >> 2;      // 0..7
    int tc = lane & 3;       // 0..3
    int warpM = (wid & 1) * 64;
    int warpN = (wid >> 1) * 32;

    int row0 = blockIdx.y * 128;
    int col0 = blockIdx.x * 128;

    int ldRow = tid >> 1;          // 0..127
    int ldCol = (tid & 1) * 8;     // 0 or 8
    const float* Ag = A + (size_t)(row0 + ldRow) * Kc + ldCol;
    const float* Wg = W + (size_t)(col0 + ldRow) * Kc + ldCol;

    float acc[4][4][4];
    #pragma unroll
    for (int mi = 0; mi < 4; mi++)
        #pragma unroll
        for (int ni = 0; ni < 4; ni++)
            #pragma unroll
            for (int e = 0; e < 4; e++) acc[mi][ni][e] = 0.f;

    // prologue: stage 0
    {
        float4 a0 = *(const float4*)Ag;
        float4 a1 = *(const float4*)(Ag + 4);
        float4 b0 = *(const float4*)Wg;
        float4 b1 = *(const float4*)(Wg + 4);
        float av[8] = {a0.x, a0.y, a0.z, a0.w, a1.x, a1.y, a1.z, a1.w};
        float bv[8] = {b0.x, b0.y, b0.z, b0.w, b1.x, b1.y, b1.z, b1.w};
        #pragma unroll
        for (int j = 0; j < 8; j++) {
            As[0][ldCol + j][ldRow] = to_tf32(av[j]);
            Bs[0][ldCol + j][ldRow] = to_tf32(bv[j]);
        }
    }
    __syncthreads();

    const int NIT = Kc >> 4;
    float4 na0, na1, nb0, nb1;
    #pragma unroll 1
    for (int it = 0; it < NIT; it++) {
        int buf = it & 1;
        if (it + 1 < NIT) {
            const float* Ag2 = Ag + (it + 1) * 16;
            const float* Wg2 = Wg + (it + 1) * 16;
            na0 = *(const float4*)Ag2;
            na1 = *(const float4*)(Ag2 + 4);
            nb0 = *(const float4*)Wg2;
            nb1 = *(const float4*)(Wg2 + 4);
        }
        #pragma unroll
        for (int kb = 0; kb < 16; kb += 8) {
            uint32_t af[4][4];
            #pragma unroll
            for (int mi = 0; mi < 4; mi++) {
                int r = warpM + mi * 16 + g;
                af[mi][0] = __float_as_uint(As[buf][kb + tc][r]);
                af[mi][1] = __float_as_uint(As[buf][kb + tc][r + 8]);
                af[mi][2] = __float_as_uint(As[buf][kb + tc + 4][r]);
                af[mi][3] = __float_as_uint(As[buf][kb + tc + 4][r + 8]);
            }
            uint32_t bf_[4][2];
            #pragma unroll
            for (int ni = 0; ni < 4; ni++) {
                int cN = warpN + ni * 8 + g;
                bf_[ni][0] = __float_as_uint(Bs[buf][kb + tc][cN]);
                bf_[ni][1] = __float_as_uint(Bs[buf][kb + tc + 4][cN]);
            }
            #pragma unroll
            for (int mi = 0; mi < 4; mi++)
                #pragma unroll
                for (int ni = 0; ni < 4; ni++)
                    mma8(acc[mi][ni], af[mi], bf_[ni]);
        }
        if (it + 1 < NIT) {
            int nb = buf ^ 1;
            float av[8] = {na0.x, na0.y, na0.z, na0.w, na1.x, na1.y, na1.z, na1.w};
            float bv[8] = {nb0.x, nb0.y, nb0.z, nb0.w, nb1.x, nb1.y, nb1.z, nb1.w};
            #pragma unroll
            for (int j = 0; j < 8; j++) {
                As[nb][ldCol + j][ldRow] = to_tf32(av[j]);
                Bs[nb][ldCol + j][ldRow] = to_tf32(bv[j]);
            }
            __syncthreads();
        }
    }

    // epilogue
    #pragma unroll
    for (int mi = 0; mi < 4; mi++) {
        #pragma unroll
        for (int ib = 0; ib < 2; ib++) {
            int m = row0 + warpM + mi * 16 + g + ib * 8;
            int orow = (m / Lb) * outBatchRows + outRowOff + (m % Lb);
            const float* resr = (EPI == 2) ? res + (size_t)m * Nc : nullptr;
            const float* gr   = (EPI == 2) ? mod + (m / Tq) * (6 * Dm) + gateOff : nullptr;
            #pragma unroll
            for (int ni = 0; ni < 4; ni++) {
                int n = col0 + warpN + ni * 8 + tc * 2;
                float v0 = acc[mi][ni][ib * 2 + 0] + bias[n];
                float v1 = acc[mi][ni][ib * 2 + 1] + bias[n + 1];
                if (EPI == 1) {
                    v0 = 0.5f * v0 * (1.f + erff(v0 * 0.70710678118654752f));
                    v1 = 0.5f * v1 * (1.f + erff(v1 * 0.70710678118654752f));
                }
                if (EPI == 2) {
                    v0 = resr[n] + gr[n] * v0;
                    v1 = resr[n + 1] + gr[n + 1] * v1;
                }
                float2 o2 = {v0, v1};
                *(float2*)&C[(size_t)orow * Nc + n] = o2;
            }
        }
    }
}

// ---- batched K/V/Q projections: z = 0..3 K(src), 4..7 V(src), 8 Q ----
__global__ __launch_bounds__(256, 2) void kvq_kernel(
    const float* __restrict__ xnorm, const float* __restrict__ bev,
    const float* __restrict__ vl, const float* __restrict__ reas,
    const float* __restrict__ k_w, const float* __restrict__ k_b,
    const float* __restrict__ v_w, const float* __restrict__ v_b,
    const float* __restrict__ qw, const float* __restrict__ qb,
    float* __restrict__ kcat, float* __restrict__ vcat, float* __restrict__ q0)
{
    __shared__ __align__(16) float As[2][16][136];
    __shared__ __align__(16) float Bs[2][16][136];
    int z = blockIdx.z;
    const float* A; const float* W; const float* bias; float* C;
    int Lb, oBR, oRO;
    if (z < 8) {
        int src = z & 3;
        if (src == 3 && blockIdx.y >= 8) return;
        A = (src == 0) ? xnorm : (src == 1) ? bev : (src == 2) ? vl : reas;
        bool isV = z >= 4;
        W    = (isV ? v_w : k_w) + (size_t)src * Dm * Dm;
        bias = (isV ? v_b : k_b) + src * Dm;
        C    = isV ? vcat : kcat;
        Lb = (src == 3) ? 256 : 512;
        oBR = KTOT; oRO = src * 512;
    } else {
        A = xnorm; W = qw; bias = qb; C = q0;
        Lb = 1 << 30; oBR = 0; oRO = 0;
    }
    gemm_core<0, 1024, 1024>(A, W, bias, C, Lb, oBR, oRO, nullptr, nullptr, 0, As, Bs);
}

// ---- batched adapter hidden: z = 0..2 ----
__global__ __launch_bounds__(256, 2) void adapter_h_kernel(
    const float* __restrict__ xnorm, const float* __restrict__ qa_w,
    const float* __restrict__ qa_b, float* __restrict__ hidden)
{
    __shared__ __align__(16) float As[2][16][136];
    __shared__ __align__(16) float Bs[2][16][136];
    int z = blockIdx.z;
    gemm_core<0, 1024, 256>(xnorm, qa_w + (size_t)z * 256 * Dm, qa_b + z * 256,
                            hidden + (size_t)z * MR * 256,
                            1 << 30, 0, 0, nullptr, nullptr, 0, As, Bs);
}

// ---- batched adapter out: z = 0..2 ----
__global__ __launch_bounds__(256, 2) void adapter_o_kernel(
    const float* __restrict__ hidden, const float* __restrict__ qa_out_w,
    const float* __restrict__ qa_out_b, float* __restrict__ qad)
{
    __shared__ __align__(16) float As[2][16][136];
    __shared__ __align__(16) float Bs[2][16][136];
    int z = blockIdx.z;
    gemm_core<0, 256, 1024>(hidden + (size_t)z * MR * 256, qa_out_w, qa_out_b,
                            qad + (size_t)z * MR * Dm,
                            1 << 30, 0, 0, nullptr, nullptr, 0, As, Bs);
}

// ---- generic (identity remap) GEMM ----
template<int EPI, int Kc, int Nc>
__global__ __launch_bounds__(256, 2) void gemm_kernel(
    const float* __restrict__ A, const float* __restrict__ W,
    const float* __restrict__ bias, float* __restrict__ C,
    const float* __restrict__ res, const float* __restrict__ mod, int gateOff)
{
    __shared__ __align__(16) float As[2][16][136];
    __shared__ __align__(16) float Bs[2][16][136];
    gemm_core<EPI, Kc, Nc>(A, W, bias, C, 1 << 30, 0, 0, res, mod, gateOff, As, Bs);
}

// ---------------- mod = silu(cond) @ adaln_w^T + adaln_b ----------------
__global__ __launch_bounds__(256) void mod_kernel(const float* __restrict__ cond,
                                                  const float* __restrict__ W,
                                                  const float* __restrict__ bb,
                                                  float* __restrict__ mod)
{
    int b = blockIdx.y;
    __shared__ float sc[Dm];
    for (int i = threadIdx.x; i < Dm; i += 256) {
        float c = cond[b * Dm + i];
        sc[i] = c / (1.f + expf(-c));
    }
    __syncthreads();
    int w = threadIdx.x >> 5, lane = threadIdx.x & 31;
    int n = blockIdx.x * 8 + w;
    const float* wr = W + (size_t)n * Dm;
    float acc = 0.f;
    for (int k = lane; k < Dm; k += 32) acc += sc[k] * wr[k];
    #pragma unroll
    for (int o = 16; o; o >>= 1) acc += __shfl_xor_sync(~0u, acc, o);
    if (lane == 0) mod[b * 6 * Dm + n] = acc + bb[n];
}

// ---------------- LayerNorm + AdaLN modulate ----------------
__global__ __launch_bounds__(256) void ln_mod_kernel(const float* __restrict__ x,
                                                     const float* __restrict__ w,
                                                     const float* __restrict__ bvec,
                                                     const float* __restrict__ mod,
                                                     int shiftOff, int scaleOff,
                                                     float* __restrict__ out)
{
    int row = blockIdx.x;
    int tid = threadIdx.x;
    float4 v = ((const float4*)(x + (size_t)row * Dm))[tid];
    float s = v.x + v.y + v.z + v.w;
    float q = v.x * v.x + v.y * v.y + v.z * v.z + v.w * v.w;
    __shared__ float rs[8], rq[8];
    #pragma unroll
    for (int o = 16; o; o >>= 1) {
        s += __shfl_xor_sync(~0u, s, o);
        q += __shfl_xor_sync(~0u, q, o);
    }
    if ((tid & 31) == 0) { rs[tid >> 5] = s; rq[tid >> 5] = q; }
    __syncthreads();
    float sum = 0.f, sq = 0.f;
    #pragma unroll
    for (int i = 0; i < 8; i++) { sum += rs[i]; sq += rq[i]; }
    float mean = sum * (1.f / Dm);
    float var  = sq * (1.f / Dm) - mean * mean;
    float inv  = rsqrtf(var + 1e-5f);
    const float* ms = mod + (row / Tq) * (6 * Dm);
    int d = tid * 4;
    float in[4] = {v.x, v.y, v.z, v.w};
    float4 ov;
    float* po = (float*)&ov;
    #pragma unroll
    for (int e = 0; e < 4; e++) {
        float xn = (in[e] - mean) * inv * w[d + e] + bvec[d + e];
        po[e] = xn * (1.f + ms[scaleOff + d + e]) + ms[shiftOff + d + e];
    }
    ((float4*)(out + (size_t)row * Dm))[tid] = ov;
}

// ---------------- RoPE table ----------------
__global__ void rope_table_kernel(float* __restrict__ c, float* __restrict__ s)
{
    int pos = blockIdx.x, j = threadIdx.x;
    float ang = (float)pos * expf(-(float)j * (9.2103403719761836f / 32.f));
    float sn, cs;
    sincosf(ang, &sn, &cs);
    c[pos * 32 + j] = cs;
    s[pos * 32 + j] = sn;
}

// ---------------- QK post: per-head RMSNorm (+ optional RoPE) ----------------
__global__ __launch_bounds__(256) void qkpost_kernel(float* __restrict__ buf,
                                                     const float* __restrict__ w,
                                                     const float* __restrict__ rc,
                                                     const float* __restrict__ rs,
                                                     int mode)
{
    int row = blockIdx.x, tid = threadIdx.x;
    float* rp = buf + (size_t)row * Dm;
    float4 v = ((float4*)rp)[tid];
    float ss = v.x * v.x + v.y * v.y + v.z * v.z + v.w * v.w;
    ss += __shfl_xor_sync(~0u, ss, 1, 16);
    ss += __shfl_xor_sync(~0u, ss, 2, 16);
    ss += __shfl_xor_sync(~0u, ss, 4, 16);
    ss += __shfl_xor_sync(~0u, ss, 8, 16);
    float inv = rsqrtf(ss * (1.f / 64.f) + 1e-6f);
    int dl = (tid & 15) * 4;
    float nv[4] = {v.x * inv * w[dl], v.y * inv * w[dl + 1],
                   v.z * inv * w[dl + 2], v.w * inv * w[dl + 3]};
    int pos = -1;
    if (mode == 1) pos = row & (Tq - 1);
    else if (mode == 2) {
        int r = row % KTOT;
        pos = (r < 512) ? r : (r < 1024) ? r - 512 : (r < 1536) ? r - 1024 : r - 1536;
    }
    if (pos >= 0) {
        float pv[4];
        #pragma unroll
        for (int e = 0; e < 4; e++) pv[e] = __shfl_xor_sync(~0u, nv[e], 8, 16);
        bool firstHalf = dl < 32;
        int jb = dl & 31;
        float4 c4 = *(const float4*)&rc[pos * 32 + jb];
        float4 s4 = *(const float4*)&rs[pos * 32 + jb];
        float cse[4] = {c4.x, c4.y, c4.z, c4.w};
        float sne[4] = {s4.x, s4.y, s4.z, s4.w};
        #pragma unroll
        for (int e = 0; e < 4; e++) {
            nv[e] = firstHalf ? (nv[e] * cse[e] - pv[e] * sne[e])
                              : (nv[e] * cse[e] + pv[e] * sne[e]);
        }
    }
    float4 o = {nv[0], nv[1], nv[2], nv[3]};
    ((float4*)rp)[tid] = o;
}

// ---------------- Flash attention (joint softmax over 4 segments) ----------------
__global__ __launch_bounds__(256) void flash_kernel(
    const float* __restrict__ q0, const float* __restrict__ q1,
    const float* __restrict__ q2, const float* __restrict__ q3,
    const float* __restrict__ kcat, const float* __restrict__ vcat,
    const float* __restrict__ temps, const float* __restrict__ sbias,
    const float* __restrict__ gating, float* __restrict__ outp)
{
    extern __shared__ float sm[];
    float* Qs = sm;               // [64 d][68]
    float* Ks = sm + 64 * 68;     // [64 d][68]
    float* Vs = sm + 2 * 64 * 68; // [key][68]
    float* Ps = sm + 3 * 64 * 68; // [qrow][68]
    __shared__ float m_sh[64], l_sh[64];

    int tid = threadIdx.x, tx = tid & 15, ty = tid >> 4;
    int h = blockIdx.y, b = blockIdx.z;
    int qbase = b * Tq + blockIdx.x * 64;
    int lr = tid >> 2, lq = tid & 3;

    if (tid < 64) { m_sh[tid] = -1e30f; l_sh[tid] = 0.f; }
    float O[4][4];
    #pragma unroll
    for (int i = 0; i < 4; i++)
        #pragma unroll
        for (int j = 0; j < 4; j++) O[i][j] = 0.f;

    const float* qp[4] = {q0, q1, q2, q3};
    const int SEGL[4] = {512, 512, 512, 256};
    const int SEGO[4] = {0, 512, 1024, 1536};
    float rg = tanhf(gating[0]);

    for (int seg = 0; seg < 4; seg++) {
        float tt = temps[seg];
        float sp = tt > 20.f ? tt : log1pf(expf(tt));
        float scale = 0.125f * (1.f + sp);
        float sb = sbias[seg];
        if (seg == 3) { scale *= rg; sb *= rg; }

        {
            const float* src = qp[seg] + (size_t)(qbase + lr) * Dm + h * HDm + lq * 16;
            #pragma unroll
            for (int q4 = 0; q4 < 4; q4++) {
                float4 t4 = ((const float4*)src)[q4];
                int d = lq * 16 + q4 * 4;
                Qs[(d + 0) * 68 + lr] = t4.x;
                Qs[(d + 1) * 68 + lr] = t4.y;
                Qs[(d + 2) * 68 + lr] = t4.z;
                Qs[(d + 3) * 68 + lr] = t4.w;
            }
        }
        int nt = SEGL[seg] >> 6;
        for (int kt = 0; kt < nt; kt++) {
            int krow = b * KTOT + SEGO[seg] + kt * 64;
            {
                const float* srk = kcat + (size_t)(krow + lr) * Dm + h * HDm + lq * 16;
                const float* srv = vcat + (size_t)(krow + lr) * Dm + h * HDm + lq * 16;
                #pragma unroll
                for (int q4 = 0; q4 < 4; q4++) {
                    float4 t4 = ((const float4*)srk)[q4];
                    int d = lq * 16 + q4 * 4;
                    Ks[(d + 0) * 68 + lr] = t4.x;
                    Ks[(d + 1) * 68 + lr] = t4.y;
                    Ks[(d + 2) * 68 + lr] = t4.z;
                    Ks[(d + 3) * 68 + lr] = t4.w;
                    *(float4*)&Vs[lr * 68 + d] = ((const float4*)srv)[q4];
                }
            }
            __syncthreads();

            float s[4][4];
            #pragma unroll
            for (int i = 0; i < 4; i++)
                #pragma unroll
                for (int j = 0; j < 4; j++) s[i][j] = 0.f;
            #pragma unroll 8
            for (int d = 0; d < 64; d++) {
                float4 qa = *(const float4*)&Qs[d * 68 + ty * 4];
                float4 kb = *(const float4*)&Ks[d * 68 + tx * 4];
                float qm[4] = {qa.x, qa.y, qa.z, qa.w};
                float kn[4] = {kb.x, kb.y, kb.z, kb.w};
                #pragma unroll
                for (int i = 0; i < 4; i++)
                    #pragma unroll
                    for (int j = 0; j < 4; j++)
                        s[i][j] += qm[i] * kn[j];
            }

            float mn[4], fac[4], rsum[4];
            #pragma unroll
            for (int i = 0; i < 4; i++) {
                float tm = -1e30f;
                #pragma unroll
                for (int j = 0; j < 4; j++) {
                    s[i][j] = s[i][j] * scale + sb;
                    tm = fmaxf(tm, s[i][j]);
                }
                #pragma unroll
                for (int o = 8; o; o >>= 1)
                    tm = fmaxf(tm, __shfl_xor_sync(~0u, tm, o, 16));
                float mo = m_sh[ty * 4 + i];
                mn[i] = fmaxf(mo, tm);
                fac[i] = __expf(mo - mn[i]);
                float sum = 0.f;
                #pragma unroll
                for (int j = 0; j < 4; j++) {
                    float p = __expf(s[i][j] - mn[i]);
                    s[i][j] = p;
                    sum += p;
                    Ps[(ty * 4 + i) * 68 + tx * 4 + j] = p;
                }
                #pragma unroll
                for (int o = 8; o; o >>= 1)
                    sum += __shfl_xor_sync(~0u, sum, o, 16);
                rsum[i] = sum;
                #pragma unroll
                for (int j = 0; j < 4; j++) O[i][j] *= fac[i];
            }
            __syncthreads();
            if (tx == 0) {
                #pragma unroll
                for (int i = 0; i < 4; i++) {
                    m_sh[ty * 4 + i] = mn[i];
                    l_sh[ty * 4 + i] = l_sh[ty * 4 + i] * fac[i] + rsum[i];
                }
            }
            #pragma unroll 8
            for (int k = 0; k < 64; k++) {
                float4 vb = *(const float4*)&Vs[k * 68 + tx * 4];
                float p0 = Ps[(ty * 4 + 0) * 68 + k];
                float p1 = Ps[(ty * 4 + 1) * 68 + k];
                float p2 = Ps[(ty * 4 + 2) * 68 + k];
                float p3 = Ps[(ty * 4 + 3) * 68 + k];
                O[0][0] += p0 * vb.x; O[0][1] += p0 * vb.y; O[0][2] += p0 * vb.z; O[0][3] += p0 * vb.w;
                O[1][0] += p1 * vb.x; O[1][1] += p1 * vb.y; O[1][2] += p1 * vb.z; O[1][3] += p1 * vb.w;
                O[2][0] += p2 * vb.x; O[2][1] += p2 * vb.y; O[2][2] += p2 * vb.z; O[2][3] += p2 * vb.w;
                O[3][0] += p3 * vb.x; O[3][1] += p3 * vb.y; O[3][2] += p3 * vb.z; O[3][3] += p3 * vb.w;
            }
            __syncthreads();
        }
    }
    #pragma unroll
    for (int i = 0; i < 4; i++) {
        float invl = 1.f / l_sh[ty * 4 + i];
        float* dst = outp + (size_t)(qbase + ty * 4 + i) * Dm + h * HDm + tx * 4;
        #pragma unroll
        for (int j = 0; j < 4; j++) dst[j] = O[i][j] * invl;
    }
}

// ---------------- launch ----------------
static float* symaddr(const void* s) {
    void* p = nullptr;
    cudaGetSymbolAddress(&p, s);
    return (float*)p;
}

extern "C" void kernel_launch(void* const* d_in, const int* in_sizes, int n_in,
                              void* d_out, int out_size)
{
    const float* x        = (const float*)d_in[0];
    const float* bev      = (const float*)d_in[1];
    const float* vl       = (const float*)d_in[2];
    const float* reas     = (const float*)d_in[3];
    const float* cond     = (const float*)d_in[4];
    const float* ln_pre_w = (const float*)d_in[5];
    const float* ln_pre_b = (const float*)d_in[6];
    const float* adaln_w  = (const float*)d_in[7];
    const float* adaln_b  = (const float*)d_in[8];
    const float* q_proj_w = (const float*)d_in[9];
    const float* q_proj_b = (const float*)d_in[10];
    const float* qa_w     = (const float*)d_in[11];
    const float* qa_b     = (const float*)d_in[12];
    const float* qa_out_w = (const float*)d_in[13];
    const float* qa_out_b = (const float*)d_in[14];
    const float* k_w      = (const float*)d_in[15];
    const float* k_b      = (const float*)d_in[16];
    const float* v_w      = (const float*)d_in[17];
    const float* v_b      = (const float*)d_in[18];
    const float* o_w      = (const float*)d_in[19];
    const float* o_b      = (const float*)d_in[20];
    const float* qn_w     = (const float*)d_in[21];
    const float* kn_w     = (const float*)d_in[22];
    const float* gating   = (const float*)d_in[23];
    const float* temps    = (const float*)d_in[24];
    const float* sbias    = (const float*)d_in[25];
    const float* ffn_ln_w = (const float*)d_in[26];
    const float* ffn_ln_b = (const float*)d_in[27];
    const float* ffn_w1   = (const float*)d_in[28];
    const float* ffn_b1   = (const float*)d_in[29];
    const float* ffn_w2   = (const float*)d_in[30];
    const float* ffn_b2   = (const float*)d_in[31];
    float* out = (float*)d_out;

    float* p_mod    = symaddr(g_mod);
    float* p_xnorm  = symaddr(g_xnorm);
    float* p_q0     = symaddr(g_q0);
    float* p_qad    = symaddr(g_qad);
    float* p_hidden = symaddr(g_hidden);
    float* p_kcat   = symaddr(g_kcat);
    float* p_vcat   = symaddr(g_vcat);
    float* p_attn   = symaddr(g_attnout);
    float* p_xa     = symaddr(g_xa);
    float* p_hln    = symaddr(g_hln);
    float* p_hff    = symaddr(g_hff);
    float* p_rcos   = symaddr(g_rcos);
    float* p_rsin   = symaddr(g_rsin);

    // 0) RoPE tables
    rope_table_kernel<<<Tq, 32>>>(p_rcos, p_rsin);

    // 1) AdaLN modulation
    mod_kernel<<<dim3(6 * Dm / 8, NB), 256>>>(cond, adaln_w, adaln_b, p_mod);

    // 2) pre-LN + modulate
    ln_mod_kernel<<<MR, 256>>>(x, ln_pre_w, ln_pre_b, p_mod, 0, Dm, p_xnorm);

    // 3) K/V (4 sources) + Q in one batched launch
    kvq_kernel<<<dim3(8, 16, 9), 256>>>(
        p_xnorm, bev, vl, reas, k_w, k_b, v_w, v_b, q_proj_w, q_proj_b,
        p_kcat, p_vcat, p_q0);

    // 4) adapters (batched over 3)
    adapter_h_kernel<<<dim3(2, 16, 3), 256>>>(p_xnorm, qa_w, qa_b, p_hidden);
    adapter_o_kernel<<<dim3(8, 16, 3), 256>>>(p_hidden, qa_out_w, qa_out_b, p_qad);

    // 5) QK-norm + RoPE
    qkpost_kernel<<<MR, 256>>>(p_q0, qn_w, p_rcos, p_rsin, 1);
    qkpost_kernel<<<3 * MR, 256>>>(p_qad, qn_w, p_rcos, p_rsin, 0);
    qkpost_kernel<<<NB * KTOT, 256>>>(p_kcat, kn_w, p_rcos, p_rsin, 2);

    // 6) flash attention
    int smemBytes = 4 * 64 * 68 * (int)sizeof(float);
    cudaFuncSetAttribute(flash_kernel, cudaFuncAttributeMaxDynamicSharedMemorySize, smemBytes);
    flash_kernel<<<dim3(Tq / 64, NH, NB), 256, smemBytes>>>(
        p_q0, p_qad, p_qad + (size_t)MR * Dm, p_qad + (size_t)2 * MR * Dm,
        p_kcat, p_vcat, temps, sbias, gating, p_attn);

    // 7) o-proj + residual + gate_attn
    gemm_kernel<2, 1024, 1024><<<dim3(8, 16), 256>>>(
        p_attn, o_w, o_b, p_xa, x, p_mod, 2 * Dm);

    // 8) FFN
    ln_mod_kernel<<<MR, 256>>>(p_xa, ffn_ln_w, ffn_ln_b, p_mod, 3 * Dm, 4 * Dm, p_hln);
    gemm_kernel<1, 1024, 4096><<<dim3(32, 16), 256>>>(
        p_hln, ffn_w1, ffn_b1, p_hff, nullptr, nullptr, 0);
    gemm_kernel<2, 4096, 1024><<<dim3(8, 16), 256>>>(
        p_hff, ffn_w2, ffn_b2, out, p_xa, p_mod, 5 * Dm);
}